// round 1
// baseline (speedup 1.0000x reference)
#include <cuda_runtime.h>
#include <math.h>

#define NNODES 50000
#define FDIM   128
#define ODIM   32

// ---------------- scratch (static device memory: no runtime alloc) ----------------
__device__ float g_h   [(size_t)NNODES * FDIM];
__device__ float g_agg [(size_t)NNODES * FDIM];
__device__ float g_xc  [(size_t)NNODES * FDIM];
__device__ float g_h2  [(size_t)NNODES * ODIM];
__device__ float g_agg2[(size_t)NNODES * ODIM];
__device__ float g_deg [NNODES];
__device__ float g_dis [NNODES];
__device__ float g_sum [FDIM];
__device__ float g_sumsq[FDIM];
__device__ int   g_is64;

// ---------------- helpers ----------------
__device__ __forceinline__ int ld_idx(const void* ei, long long pos, int is64) {
    if (is64) return (int)((const long long*)ei)[pos];
    return ((const int*)ei)[pos];
}

// Detect int64 vs int32 edge_index: if dtype is int64, the high 32-bit word of
// every index (< 50000) is zero. If int32, those words are random indices.
__global__ void k_detect(const unsigned* __restrict__ w) {
    __shared__ int s;
    if (threadIdx.x == 0) s = 1;
    __syncthreads();
    for (int i = threadIdx.x; i < 1024; i += blockDim.x)
        if (w[2 * i + 1] != 0u) atomicAnd(&s, 0);
    __syncthreads();
    if (threadIdx.x == 0) g_is64 = s;
}

__global__ void k_zero_deg() {
    int i = blockIdx.x * blockDim.x + threadIdx.x;
    if (i < NNODES) g_deg[i] = 0.0f;
}

__global__ void k_hist(const void* __restrict__ ei, int E) {
    int e = blockIdx.x * blockDim.x + threadIdx.x;
    if (e >= E) return;
    int is64 = g_is64;
    int dst = ld_idx(ei, (long long)E + e, is64);
    atomicAdd(&g_deg[dst], 1.0f);
}

__global__ void k_dis() {
    int i = blockIdx.x * blockDim.x + threadIdx.x;
    if (i < NNODES) g_dis[i] = rsqrtf(g_deg[i] + 1.0f);
}

// ---------------- GEMM: H[n,M] = X[n,128] @ W[128,M] ----------------
// Block: (M/4)*8 threads. 32 rows per tile. W staged fully in smem,
// X tile staged (stride 132 to kill bank conflicts). 4x4 register tile/thread.
template <int M>
__global__ void k_gemm(const float* __restrict__ X, const float* __restrict__ W,
                       float* __restrict__ H, int n) {
    extern __shared__ float sm[];
    float* sW = sm;              // 128*M
    float* sX = sm + 128 * M;    // 32*132
    const int T = blockDim.x;

    for (int i = threadIdx.x; i < 128 * M / 4; i += T)
        ((float4*)sW)[i] = ((const float4*)W)[i];

    const int cg = threadIdx.x % (M / 4);
    const int rg = threadIdx.x / (M / 4);
    const int ntiles = (n + 31) / 32;

    for (int tile = blockIdx.x; tile < ntiles; tile += gridDim.x) {
        int r0 = tile * 32;
        __syncthreads();   // covers W load (first iter) and previous compute
        for (int i = threadIdx.x; i < 32 * 32; i += T) {   // 1024 float4
            int rr = i >> 5, cc = i & 31;
            float4 v = make_float4(0.f, 0.f, 0.f, 0.f);
            if (r0 + rr < n)
                v = ((const float4*)(X + (long long)(r0 + rr) * 128))[cc];
            *(float4*)&sX[rr * 132 + cc * 4] = v;
        }
        __syncthreads();

        float acc[4][4];
#pragma unroll
        for (int i = 0; i < 4; i++)
#pragma unroll
            for (int j = 0; j < 4; j++) acc[i][j] = 0.0f;

#pragma unroll 8
        for (int k = 0; k < 128; k++) {
            float4 wv = *(float4*)&sW[k * M + cg * 4];
#pragma unroll
            for (int i = 0; i < 4; i++) {
                float xv = sX[(rg * 4 + i) * 132 + k];
                acc[i][0] += xv * wv.x;
                acc[i][1] += xv * wv.y;
                acc[i][2] += xv * wv.z;
                acc[i][3] += xv * wv.w;
            }
        }
#pragma unroll
        for (int i = 0; i < 4; i++) {
            int r = r0 + rg * 4 + i;
            if (r < n)
                *(float4*)&H[(long long)r * M + cg * 4] =
                    make_float4(acc[i][0], acc[i][1], acc[i][2], acc[i][3]);
        }
    }
}

// agg = h * (dis*dis) + b   (self-loop term + bias; also initializes agg)
template <int M>
__global__ void k_init(const float* __restrict__ H, const float* __restrict__ b,
                       float* __restrict__ AGG, int n) {
    long long i = (long long)blockIdx.x * blockDim.x + threadIdx.x;
    long long tot = (long long)n * (M / 4);
    if (i >= tot) return;
    int row = (int)(i / (M / 4));
    int c4 = (int)(i % (M / 4));
    float d = g_dis[row];
    float d2 = d * d;
    float4 h = ((const float4*)H)[i];
    float4 bb = ((const float4*)b)[c4];
    ((float4*)AGG)[i] = make_float4(fmaf(h.x, d2, bb.x), fmaf(h.y, d2, bb.y),
                                    fmaf(h.z, d2, bb.z), fmaf(h.w, d2, bb.w));
}

// edge scatter: AGG[dst] += h[src] * dis[src]*dis[dst], vector red.add
template <int M>
__global__ void k_scatter(const void* __restrict__ ei, const float* __restrict__ H,
                          float* __restrict__ AGG, int E) {
    const int LPE = M / 4;                       // lanes per edge (32 or 8)
    long long t = (long long)blockIdx.x * blockDim.x + threadIdx.x;
    if (t >= (long long)E * LPE) return;
    int e = (int)(t / LPE);
    int lane = (int)(t % LPE);
    int is64 = g_is64;
    int src = ld_idx(ei, e, is64);
    int dst = ld_idx(ei, (long long)E + e, is64);
    float norm = g_dis[src] * g_dis[dst];
    float4 v = ((const float4*)(H + (long long)src * M))[lane];
    float* p = AGG + (long long)dst * M + lane * 4;
    asm volatile("red.global.add.v4.f32 [%0], {%1,%2,%3,%4};"
                 :: "l"(p), "f"(v.x * norm), "f"(v.y * norm),
                    "f"(v.z * norm), "f"(v.w * norm)
                 : "memory");
}

__global__ void k_zero_stats() {
    int i = threadIdx.x;
    if (i < FDIM) { g_sum[i] = 0.0f; g_sumsq[i] = 0.0f; }
}

// per-column sum / sumsq over rows (block-partial + atomic combine)
__global__ void k_stats(const float* __restrict__ AGG, int n) {
    int c = threadIdx.x;   // 128 threads
    float s = 0.0f, s2 = 0.0f;
    for (int r = blockIdx.x; r < n; r += gridDim.x) {
        float v = AGG[(long long)r * FDIM + c];
        s += v;
        s2 += v * v;
    }
    atomicAdd(&g_sum[c], s);
    atomicAdd(&g_sumsq[c], s2);
}

// y = relu(BN(agg)) + xres  -> XOUT
__global__ void k_apply(const float* __restrict__ AGG, const float* __restrict__ gam,
                        const float* __restrict__ bet, const float* __restrict__ XRES,
                        float* __restrict__ XOUT, int n) {
    long long i = (long long)blockIdx.x * blockDim.x + threadIdx.x;
    long long tot = (long long)n * (FDIM / 4);
    if (i >= tot) return;
    int c4 = (int)(i % (FDIM / 4));
    float inv = 1.0f / (float)n;
    float4 a = ((const float4*)AGG)[i];
    float4 r = ((const float4*)XRES)[i];
    float av[4] = {a.x, a.y, a.z, a.w};
    float rv[4] = {r.x, r.y, r.z, r.w};
    float o[4];
#pragma unroll
    for (int j = 0; j < 4; j++) {
        int c = c4 * 4 + j;
        float mu = g_sum[c] * inv;
        float var = g_sumsq[c] * inv - mu * mu;
        float rstd = rsqrtf(var + 1e-5f);
        float y = (av[j] - mu) * rstd * gam[c] + bet[c];
        o[j] = fmaxf(y, 0.0f) + rv[j];
    }
    ((float4*)XOUT)[i] = make_float4(o[0], o[1], o[2], o[3]);
}

// log_softmax over 32 classes: one warp per row
__global__ void k_lsm(const float* __restrict__ A, float* __restrict__ out, int n) {
    int r = blockIdx.x * (blockDim.x >> 5) + (threadIdx.x >> 5);
    int lane = threadIdx.x & 31;
    if (r >= n) return;
    float v = A[(long long)r * ODIM + lane];
    float m = v;
#pragma unroll
    for (int o = 16; o; o >>= 1) m = fmaxf(m, __shfl_xor_sync(0xffffffffu, m, o));
    float e = expf(v - m);
    float s = e;
#pragma unroll
    for (int o = 16; o; o >>= 1) s += __shfl_xor_sync(0xffffffffu, s, o);
    out[(long long)r * ODIM + lane] = v - m - logf(s);
}

// ---------------- launch ----------------
extern "C" void kernel_launch(void* const* d_in, const int* in_sizes, int n_in,
                              void* d_out, int out_size) {
    const float* x   = (const float*)d_in[0];
    const void*  ei  = d_in[1];
    const float* W0  = (const float*)d_in[2];
    const float* b0  = (const float*)d_in[3];
    const float* gm0 = (const float*)d_in[4];
    const float* be0 = (const float*)d_in[5];
    const float* W1  = (const float*)d_in[6];
    const float* b1  = (const float*)d_in[7];
    const float* gm1 = (const float*)d_in[8];
    const float* be1 = (const float*)d_in[9];
    const float* W2  = (const float*)d_in[10];
    const float* b2  = (const float*)d_in[11];
    float* out = (float*)d_out;

    const int n = in_sizes[0] / FDIM;   // 50000
    const int E = in_sizes[1] / 2;      // 800000 (element count same for i32/i64)

    float *p_h, *p_agg, *p_xc, *p_h2, *p_agg2;
    cudaGetSymbolAddress((void**)&p_h, g_h);
    cudaGetSymbolAddress((void**)&p_agg, g_agg);
    cudaGetSymbolAddress((void**)&p_xc, g_xc);
    cudaGetSymbolAddress((void**)&p_h2, g_h2);
    cudaGetSymbolAddress((void**)&p_agg2, g_agg2);

    const int SMEM128 = 128 * 128 * 4 + 32 * 132 * 4;   // 82432
    const int SMEM32  = 128 * 32 * 4 + 32 * 132 * 4;    // 33280
    cudaFuncSetAttribute(k_gemm<128>, cudaFuncAttributeMaxDynamicSharedMemorySize, SMEM128);
    cudaFuncSetAttribute(k_gemm<32>,  cudaFuncAttributeMaxDynamicSharedMemorySize, SMEM32);

    const int elem128_blocks = (int)(((long long)n * (FDIM / 4) + 255) / 256);
    const int scat128_blocks = (int)(((long long)E * 32 + 255) / 256);
    const int elem32_blocks  = (int)(((long long)n * (ODIM / 4) + 255) / 256);
    const int scat32_blocks  = (int)(((long long)E * 8 + 255) / 256);

    k_detect<<<1, 256>>>((const unsigned*)ei);
    k_zero_deg<<<(NNODES + 255) / 256, 256>>>();
    k_hist<<<(E + 255) / 256, 256>>>(ei, E);
    k_dis<<<(NNODES + 255) / 256, 256>>>();

    // ---- block 0 ----
    k_gemm<128><<<296, 256, SMEM128>>>(x, W0, p_h, n);
    k_init<128><<<elem128_blocks, 256>>>(p_h, b0, p_agg, n);
    k_zero_stats<<<1, 128>>>();
    k_scatter<128><<<scat128_blocks, 256>>>(ei, p_h, p_agg, E);
    k_stats<<<512, 128>>>(p_agg, n);
    k_apply<<<elem128_blocks, 256>>>(p_agg, gm0, be0, x, p_xc, n);

    // ---- block 1 ----
    k_gemm<128><<<296, 256, SMEM128>>>(p_xc, W1, p_h, n);
    k_init<128><<<elem128_blocks, 256>>>(p_h, b1, p_agg, n);
    k_zero_stats<<<1, 128>>>();
    k_scatter<128><<<scat128_blocks, 256>>>(ei, p_h, p_agg, E);
    k_stats<<<512, 128>>>(p_agg, n);
    k_apply<<<elem128_blocks, 256>>>(p_agg, gm1, be1, p_xc, p_xc, n);

    // ---- final conv + log_softmax ----
    k_gemm<32><<<888, 64, SMEM32>>>(p_xc, W2, p_h2, n);
    k_init<32><<<elem32_blocks, 256>>>(p_h2, b2, p_agg2, n);
    k_scatter<32><<<scat32_blocks, 256>>>(ei, p_h2, p_agg2, E);
    k_lsm<<<(n + 7) / 8, 256>>>(p_agg2, out, n);
}

// round 3
// speedup vs baseline: 1.1412x; 1.1412x over previous
#include <cuda_runtime.h>
#include <math.h>
#include <stdint.h>

#define NNODES 50000
#define EMAX   800000
#define FDIM   128
#define ODIM   32

// ---------------- scratch (static device memory) ----------------
__device__ float g_h   [(size_t)NNODES * FDIM];
__device__ float g_agg [(size_t)NNODES * FDIM];
__device__ float g_xc  [(size_t)NNODES * FDIM];
__device__ float g_h2  [(size_t)NNODES * ODIM];
__device__ float g_dis [NNODES];
__device__ float g_sum [FDIM];
__device__ float g_sumsq[FDIM];
__device__ int   g_cnt [NNODES];
__device__ int   g_cur [NNODES];
__device__ int   g_off [NNODES + 1];
__device__ int   g_esrc[EMAX];
__device__ int   g_is64;

// ---------------- helpers ----------------
__device__ __forceinline__ int ld_idx(const void* ei, long long pos, int is64) {
    if (is64) return (int)((const long long*)ei)[pos];
    return ((const int*)ei)[pos];
}

// int64 vs int32 edge_index detection (high words all zero => int64)
__global__ void k_detect(const unsigned* __restrict__ w) {
    __shared__ int s;
    if (threadIdx.x == 0) s = 1;
    __syncthreads();
    for (int i = threadIdx.x; i < 1024; i += blockDim.x)
        if (w[2 * i + 1] != 0u) atomicAnd(&s, 0);
    __syncthreads();
    if (threadIdx.x == 0) g_is64 = s;
}

__global__ void k_zero_int() {
    int i = blockIdx.x * blockDim.x + threadIdx.x;
    if (i < NNODES) { g_cnt[i] = 0; g_cur[i] = 0; }
}

__global__ void k_hist(const void* __restrict__ ei, int E) {
    int e = blockIdx.x * blockDim.x + threadIdx.x;
    if (e >= E) return;
    int dst = ld_idx(ei, (long long)E + e, g_is64);
    atomicAdd(&g_cnt[dst], 1);
}

__global__ void k_dis() {
    int i = blockIdx.x * blockDim.x + threadIdx.x;
    if (i < NNODES) g_dis[i] = rsqrtf((float)g_cnt[i] + 1.0f);
}

// single-block exclusive prefix scan of g_cnt -> g_off
__global__ void k_prefix() {
    __shared__ int ps[1024];
    const int t = threadIdx.x;
    const int CH = (NNODES + 1023) / 1024;          // 49
    int lo = t * CH, hi = min(lo + CH, NNODES);
    int s = 0;
    for (int i = lo; i < hi; i++) s += g_cnt[i];
    ps[t] = s;
    __syncthreads();
    for (int off = 1; off < 1024; off <<= 1) {
        int v = ps[t];
        int add = (t >= off) ? ps[t - off] : 0;
        __syncthreads();
        ps[t] = v + add;
        __syncthreads();
    }
    int run = (t > 0) ? ps[t - 1] : 0;              // exclusive prefix
    for (int i = lo; i < hi; i++) { g_off[i] = run; run += g_cnt[i]; }
    if (t == 1023) g_off[NNODES] = run;             // == E
}

__global__ void k_fill(const void* __restrict__ ei, int E) {
    int e = blockIdx.x * blockDim.x + threadIdx.x;
    if (e >= E) return;
    int is64 = g_is64;
    int src = ld_idx(ei, e, is64);
    int dst = ld_idx(ei, (long long)E + e, is64);
    int pos = atomicAdd(&g_cur[dst], 1);
    g_esrc[g_off[dst] + pos] = src;
}

// ---------------- GEMM: H[n,M] = X[n,128] @ W[128,M] ----------------
template <int M>
__global__ void k_gemm(const float* __restrict__ X, const float* __restrict__ W,
                       float* __restrict__ H, int n) {
    extern __shared__ float sm[];
    float* sW = sm;              // 128*M
    float* sX = sm + 128 * M;    // 32*132
    const int T = blockDim.x;

    for (int i = threadIdx.x; i < 128 * M / 4; i += T)
        ((float4*)sW)[i] = ((const float4*)W)[i];

    const int cg = threadIdx.x % (M / 4);
    const int rg = threadIdx.x / (M / 4);
    const int ntiles = (n + 31) / 32;

    for (int tile = blockIdx.x; tile < ntiles; tile += gridDim.x) {
        int r0 = tile * 32;
        __syncthreads();
        for (int i = threadIdx.x; i < 32 * 32; i += T) {
            int rr = i >> 5, cc = i & 31;
            float4 v = make_float4(0.f, 0.f, 0.f, 0.f);
            if (r0 + rr < n)
                v = ((const float4*)(X + (long long)(r0 + rr) * 128))[cc];
            *(float4*)&sX[rr * 132 + cc * 4] = v;
        }
        __syncthreads();

        float acc[4][4];
#pragma unroll
        for (int i = 0; i < 4; i++)
#pragma unroll
            for (int j = 0; j < 4; j++) acc[i][j] = 0.0f;

#pragma unroll 8
        for (int k = 0; k < 128; k++) {
            float4 wv = *(float4*)&sW[k * M + cg * 4];
#pragma unroll
            for (int i = 0; i < 4; i++) {
                float xv = sX[(rg * 4 + i) * 132 + k];
                acc[i][0] += xv * wv.x;
                acc[i][1] += xv * wv.y;
                acc[i][2] += xv * wv.z;
                acc[i][3] += xv * wv.w;
            }
        }
#pragma unroll
        for (int i = 0; i < 4; i++) {
            int r = r0 + rg * 4 + i;
            if (r < n)
                *(float4*)&H[(long long)r * M + cg * 4] =
                    make_float4(acc[i][0], acc[i][1], acc[i][2], acc[i][3]);
        }
    }
}

// ---------------- CSR aggregation (128-wide): warp per dst node ----------------
// AGG[v] = b + h[v]*dis[v]^2 + sum_{e: dst=v} h[src_e] * dis[src_e]*dis[v]
__global__ void k_agg128(const float* __restrict__ H, const float* __restrict__ bias,
                         float* __restrict__ AGG, int n) {
    int v = (blockIdx.x * blockDim.x + threadIdx.x) >> 5;
    if (v >= n) return;
    const int lane = threadIdx.x & 31;
    const float dv = g_dis[v];
    const int e0 = g_off[v], e1 = g_off[v + 1];

    float4 acc = ((const float4*)bias)[lane];
    {
        float4 hv = ((const float4*)(H + (long long)v * FDIM))[lane];
        float d2 = dv * dv;
        acc.x = fmaf(hv.x, d2, acc.x);
        acc.y = fmaf(hv.y, d2, acc.y);
        acc.z = fmaf(hv.z, d2, acc.z);
        acc.w = fmaf(hv.w, d2, acc.w);
    }
    int e = e0;
    for (; e + 1 < e1; e += 2) {                    // unroll-2 for MLP
        int s0 = __ldg(&g_esrc[e]);
        int s1 = __ldg(&g_esrc[e + 1]);
        float n0 = g_dis[s0] * dv;
        float n1 = g_dis[s1] * dv;
        float4 a = ((const float4*)(H + (long long)s0 * FDIM))[lane];
        float4 b = ((const float4*)(H + (long long)s1 * FDIM))[lane];
        acc.x = fmaf(a.x, n0, acc.x); acc.y = fmaf(a.y, n0, acc.y);
        acc.z = fmaf(a.z, n0, acc.z); acc.w = fmaf(a.w, n0, acc.w);
        acc.x = fmaf(b.x, n1, acc.x); acc.y = fmaf(b.y, n1, acc.y);
        acc.z = fmaf(b.z, n1, acc.z); acc.w = fmaf(b.w, n1, acc.w);
    }
    if (e < e1) {
        int s0 = __ldg(&g_esrc[e]);
        float n0 = g_dis[s0] * dv;
        float4 a = ((const float4*)(H + (long long)s0 * FDIM))[lane];
        acc.x = fmaf(a.x, n0, acc.x); acc.y = fmaf(a.y, n0, acc.y);
        acc.z = fmaf(a.z, n0, acc.z); acc.w = fmaf(a.w, n0, acc.w);
    }
    ((float4*)(AGG + (long long)v * FDIM))[lane] = acc;
}

// ---------------- CSR aggregation (32-wide) fused with log_softmax ----------------
__global__ void k_agg32_lsm(const float* __restrict__ H2, const float* __restrict__ bias,
                            float* __restrict__ out, int n) {
    int v = (blockIdx.x * blockDim.x + threadIdx.x) >> 5;
    if (v >= n) return;
    const int lane = threadIdx.x & 31;
    const float dv = g_dis[v];
    const int e0 = g_off[v], e1 = g_off[v + 1];

    float acc = bias[lane] + H2[(long long)v * ODIM + lane] * dv * dv;
    int e = e0;
    for (; e + 1 < e1; e += 2) {
        int s0 = __ldg(&g_esrc[e]);
        int s1 = __ldg(&g_esrc[e + 1]);
        float n0 = g_dis[s0] * dv;
        float n1 = g_dis[s1] * dv;
        float a = H2[(long long)s0 * ODIM + lane];
        float b = H2[(long long)s1 * ODIM + lane];
        acc = fmaf(a, n0, acc);
        acc = fmaf(b, n1, acc);
    }
    if (e < e1) {
        int s0 = __ldg(&g_esrc[e]);
        acc = fmaf(H2[(long long)s0 * ODIM + lane], g_dis[s0] * dv, acc);
    }
    // log-softmax over the 32 classes held by this warp
    float m = acc;
#pragma unroll
    for (int o = 16; o; o >>= 1) m = fmaxf(m, __shfl_xor_sync(0xffffffffu, m, o));
    float ex = expf(acc - m);
    float s = ex;
#pragma unroll
    for (int o = 16; o; o >>= 1) s += __shfl_xor_sync(0xffffffffu, s, o);
    out[(long long)v * ODIM + lane] = acc - m - logf(s);
}

// ---------------- BN stats / apply ----------------
__global__ void k_zero_stats() {
    int i = threadIdx.x;
    if (i < FDIM) { g_sum[i] = 0.0f; g_sumsq[i] = 0.0f; }
}
__global__ void k_stats(const float* __restrict__ AGG, int n) {
    int c = threadIdx.x;
    float s = 0.0f, s2 = 0.0f;
    for (int r = blockIdx.x; r < n; r += gridDim.x) {
        float v = AGG[(long long)r * FDIM + c];
        s += v;
        s2 += v * v;
    }
    atomicAdd(&g_sum[c], s);
    atomicAdd(&g_sumsq[c], s2);
}
__global__ void k_apply(const float* __restrict__ AGG, const float* __restrict__ gam,
                        const float* __restrict__ bet, const float* __restrict__ XRES,
                        float* __restrict__ XOUT, int n) {
    long long i = (long long)blockIdx.x * blockDim.x + threadIdx.x;
    long long tot = (long long)n * (FDIM / 4);
    if (i >= tot) return;
    int c4 = (int)(i % (FDIM / 4));
    float inv = 1.0f / (float)n;
    float4 a = ((const float4*)AGG)[i];
    float4 r = ((const float4*)XRES)[i];
    float av[4] = {a.x, a.y, a.z, a.w};
    float rv[4] = {r.x, r.y, r.z, r.w};
    float o[4];
#pragma unroll
    for (int j = 0; j < 4; j++) {
        int c = c4 * 4 + j;
        float mu = g_sum[c] * inv;
        float var = g_sumsq[c] * inv - mu * mu;
        float rstd = rsqrtf(var + 1e-5f);
        float y = (av[j] - mu) * rstd * gam[c] + bet[c];
        o[j] = fmaxf(y, 0.0f) + rv[j];
    }
    ((float4*)XOUT)[i] = make_float4(o[0], o[1], o[2], o[3]);
}

// ---------------- launch ----------------
extern "C" void kernel_launch(void* const* d_in, const int* in_sizes, int n_in,
                              void* d_out, int out_size) {
    const float* x   = (const float*)d_in[0];
    const void*  ei  = d_in[1];
    const float* W0  = (const float*)d_in[2];
    const float* b0  = (const float*)d_in[3];
    const float* gm0 = (const float*)d_in[4];
    const float* be0 = (const float*)d_in[5];
    const float* W1  = (const float*)d_in[6];
    const float* b1  = (const float*)d_in[7];
    const float* gm1 = (const float*)d_in[8];
    const float* be1 = (const float*)d_in[9];
    const float* W2  = (const float*)d_in[10];
    const float* b2  = (const float*)d_in[11];
    float* out = (float*)d_out;

    const int n = in_sizes[0] / FDIM;   // 50000
    const int E = in_sizes[1] / 2;      // 800000

    float *p_h, *p_agg, *p_xc, *p_h2;
    cudaGetSymbolAddress((void**)&p_h, g_h);
    cudaGetSymbolAddress((void**)&p_agg, g_agg);
    cudaGetSymbolAddress((void**)&p_xc, g_xc);
    cudaGetSymbolAddress((void**)&p_h2, g_h2);

    const int SMEM128 = 128 * 128 * 4 + 32 * 132 * 4;   // 82432
    const int SMEM32  = 128 * 32 * 4 + 32 * 132 * 4;    // 33280
    cudaFuncSetAttribute(k_gemm<128>, cudaFuncAttributeMaxDynamicSharedMemorySize, SMEM128);
    cudaFuncSetAttribute(k_gemm<32>,  cudaFuncAttributeMaxDynamicSharedMemorySize, SMEM32);

    const int elem128_blocks = (int)(((long long)n * (FDIM / 4) + 255) / 256);
    const int node_warp_blocks = (n + 7) / 8;           // 8 warps per 256-thread block

    // ---- graph preprocessing (CSR build) ----
    k_detect<<<1, 256>>>((const unsigned*)ei);
    k_zero_int<<<(NNODES + 255) / 256, 256>>>();
    k_hist<<<(E + 255) / 256, 256>>>(ei, E);
    k_dis<<<(NNODES + 255) / 256, 256>>>();
    k_prefix<<<1, 1024>>>();
    k_fill<<<(E + 255) / 256, 256>>>(ei, E);

    // ---- block 0 ----
    k_gemm<128><<<296, 256, SMEM128>>>(x, W0, p_h, n);
    k_agg128<<<node_warp_blocks, 256>>>(p_h, b0, p_agg, n);
    k_zero_stats<<<1, 128>>>();
    k_stats<<<256, 128>>>(p_agg, n);
    k_apply<<<elem128_blocks, 256>>>(p_agg, gm0, be0, x, p_xc, n);

    // ---- block 1 ----
    k_gemm<128><<<296, 256, SMEM128>>>(p_xc, W1, p_h, n);
    k_agg128<<<node_warp_blocks, 256>>>(p_h, b1, p_agg, n);
    k_zero_stats<<<1, 128>>>();
    k_stats<<<256, 128>>>(p_agg, n);
    k_apply<<<elem128_blocks, 256>>>(p_agg, gm1, be1, p_xc, p_xc, n);

    // ---- final conv + fused log_softmax ----
    k_gemm<32><<<888, 64, SMEM32>>>(p_xc, W2, p_h2, n);
    k_agg32_lsm<<<node_warp_blocks, 256>>>(p_h2, b2, out, n);
}

// round 4
// speedup vs baseline: 1.3866x; 1.2151x over previous
#include <cuda_runtime.h>
#include <cuda_bf16.h>
#include <math.h>
#include <stdint.h>

#define NNODES 50000
#define EMAX   800000
#define FDIM   128
#define ODIM   32
#define PAD    136          // bf16 elems per padded smem row (272B: conflict-free ldmatrix)

// ---------------- scratch (static device memory) ----------------
__device__ float g_h   [(size_t)NNODES * FDIM];
__device__ float g_agg [(size_t)NNODES * FDIM];
__device__ float g_xc  [(size_t)NNODES * FDIM];
__device__ float g_h2  [(size_t)NNODES * ODIM];
__device__ float g_dis [NNODES];
__device__ float g_sum [FDIM];
__device__ float g_sumsq[FDIM];
__device__ int   g_cnt [NNODES];
__device__ int   g_cur [NNODES];
__device__ int   g_off [NNODES + 1];
__device__ int   g_esrc[EMAX];
__device__ int   g_is64;

// ---------------- helpers ----------------
__device__ __forceinline__ int ld_idx(const void* ei, long long pos, int is64) {
    if (is64) return (int)((const long long*)ei)[pos];
    return ((const int*)ei)[pos];
}
__device__ __forceinline__ uint32_t smem_u32(const void* p) {
    uint32_t a;
    asm("{ .reg .u64 t; cvta.to.shared.u64 t, %1; cvt.u32.u64 %0, t; }" : "=r"(a) : "l"(p));
    return a;
}
__device__ __forceinline__ void ldsm_x4(uint32_t* r, uint32_t addr) {
    asm volatile("ldmatrix.sync.aligned.m8n8.x4.shared.b16 {%0,%1,%2,%3}, [%4];"
                 : "=r"(r[0]), "=r"(r[1]), "=r"(r[2]), "=r"(r[3]) : "r"(addr));
}
__device__ __forceinline__ void ldsm_x2t(uint32_t* r, uint32_t addr) {
    asm volatile("ldmatrix.sync.aligned.m8n8.x2.trans.shared.b16 {%0,%1}, [%2];"
                 : "=r"(r[0]), "=r"(r[1]) : "r"(addr));
}
__device__ __forceinline__ void mma_bf16(float* c, const uint32_t* a, const uint32_t* b) {
    asm volatile("mma.sync.aligned.m16n8k16.row.col.f32.bf16.bf16.f32 "
                 "{%0,%1,%2,%3}, {%4,%5,%6,%7}, {%8,%9}, {%0,%1,%2,%3};"
                 : "+f"(c[0]), "+f"(c[1]), "+f"(c[2]), "+f"(c[3])
                 : "r"(a[0]), "r"(a[1]), "r"(a[2]), "r"(a[3]), "r"(b[0]), "r"(b[1]));
}
// split fp32 x4 -> hi/lo bf16 pairs packed as uint2 each
__device__ __forceinline__ void split4(float4 v, uint2& hi, uint2& lo) {
    __nv_bfloat16 h0 = __float2bfloat16(v.x), h1 = __float2bfloat16(v.y);
    __nv_bfloat16 h2 = __float2bfloat16(v.z), h3 = __float2bfloat16(v.w);
    __nv_bfloat16 l0 = __float2bfloat16(v.x - __bfloat162float(h0));
    __nv_bfloat16 l1 = __float2bfloat16(v.y - __bfloat162float(h1));
    __nv_bfloat16 l2 = __float2bfloat16(v.z - __bfloat162float(h2));
    __nv_bfloat16 l3 = __float2bfloat16(v.w - __bfloat162float(h3));
    __nv_bfloat162 hp0 = __halves2bfloat162(h0, h1), hp1 = __halves2bfloat162(h2, h3);
    __nv_bfloat162 lp0 = __halves2bfloat162(l0, l1), lp1 = __halves2bfloat162(l2, l3);
    hi = make_uint2(*(uint32_t*)&hp0, *(uint32_t*)&hp1);
    lo = make_uint2(*(uint32_t*)&lp0, *(uint32_t*)&lp1);
}

// ---------------- graph preprocessing (CSR) ----------------
__global__ void k_detect(const unsigned* __restrict__ w) {
    __shared__ int s;
    if (threadIdx.x == 0) s = 1;
    __syncthreads();
    for (int i = threadIdx.x; i < 1024; i += blockDim.x)
        if (w[2 * i + 1] != 0u) atomicAnd(&s, 0);
    __syncthreads();
    if (threadIdx.x == 0) g_is64 = s;
}
__global__ void k_zero_int() {
    int i = blockIdx.x * blockDim.x + threadIdx.x;
    if (i < NNODES) { g_cnt[i] = 0; g_cur[i] = 0; }
}
__global__ void k_hist(const void* __restrict__ ei, int E) {
    int e = blockIdx.x * blockDim.x + threadIdx.x;
    if (e >= E) return;
    int dst = ld_idx(ei, (long long)E + e, g_is64);
    atomicAdd(&g_cnt[dst], 1);
}
__global__ void k_dis() {
    int i = blockIdx.x * blockDim.x + threadIdx.x;
    if (i < NNODES) g_dis[i] = rsqrtf((float)g_cnt[i] + 1.0f);
}
__global__ void k_prefix() {
    __shared__ int ps[1024];
    const int t = threadIdx.x;
    const int CH = (NNODES + 1023) / 1024;
    int lo = t * CH, hi = min(lo + CH, NNODES);
    int s = 0;
    for (int i = lo; i < hi; i++) s += g_cnt[i];
    ps[t] = s;
    __syncthreads();
    for (int off = 1; off < 1024; off <<= 1) {
        int v = ps[t];
        int add = (t >= off) ? ps[t - off] : 0;
        __syncthreads();
        ps[t] = v + add;
        __syncthreads();
    }
    int run = (t > 0) ? ps[t - 1] : 0;
    for (int i = lo; i < hi; i++) { g_off[i] = run; run += g_cnt[i]; }
    if (t == 1023) g_off[NNODES] = run;
}
__global__ void k_fill(const void* __restrict__ ei, int E) {
    int e = blockIdx.x * blockDim.x + threadIdx.x;
    if (e >= E) return;
    int is64 = g_is64;
    int src = ld_idx(ei, e, is64);
    int dst = ld_idx(ei, (long long)E + e, is64);
    int pos = atomicAdd(&g_cur[dst], 1);
    g_esrc[g_off[dst] + pos] = src;
}

// ---------------- tensor-core GEMM 128x128 (bf16 pair-split, 3 passes) ----------------
// H[r,c] = sum_k X[r,k] W[k,c];  AGG[r,c] = H[r,c]*dis[r]^2 + bias[c]
// CTA: 64 rows, 128 threads (4 warps, 2m x 2n). smem: A hi/lo 64xPAD, B hi/lo 128xPAD.
#define A_HI_OFF 0
#define A_LO_OFF (64 * PAD * 2)
#define B_HI_OFF (2 * 64 * PAD * 2)
#define B_LO_OFF (B_HI_OFF + 128 * PAD * 2)
#define MMA_SMEM (B_LO_OFF + 128 * PAD * 2)   // 104448 bytes

__global__ void __launch_bounds__(128, 2)
k_mma128(const float* __restrict__ X, const float* __restrict__ W,
         const float* __restrict__ bias, float* __restrict__ H,
         float* __restrict__ AGG, int n) {
    extern __shared__ char smem[];
    const int tid = threadIdx.x;

    // stage W [128k x 128n] -> B hi/lo
    for (int i = tid; i < 4096; i += 128) {
        float4 w = __ldg(&((const float4*)W)[i]);
        int k = i >> 5, c4 = i & 31;
        uint2 hi, lo;
        split4(w, hi, lo);
        int boff = (k * PAD + c4 * 4) * 2;
        *(uint2*)(smem + B_HI_OFF + boff) = hi;
        *(uint2*)(smem + B_LO_OFF + boff) = lo;
    }
    // stage X tile [64 x 128] -> A hi/lo
    const int r0 = (int)blockIdx.x * 64;
    for (int i = tid; i < 2048; i += 128) {
        int row = i >> 5, c4 = i & 31;
        int r = r0 + row;
        float4 v = (r < n) ? __ldg(&((const float4*)(X + (size_t)r * 128))[c4])
                           : make_float4(0.f, 0.f, 0.f, 0.f);
        uint2 hi, lo;
        split4(v, hi, lo);
        int aoff = (row * PAD + c4 * 4) * 2;
        *(uint2*)(smem + A_HI_OFF + aoff) = hi;
        *(uint2*)(smem + A_LO_OFF + aoff) = lo;
    }
    __syncthreads();

    const int lane = tid & 31, wid = tid >> 5;
    const int m0 = (wid & 1) * 32;        // warp rows base (within tile)
    const int n0 = (wid >> 1) * 64;       // warp cols base
    const uint32_t sb = smem_u32(smem);

    const uint32_t a_lane = (uint32_t)(lane & 15) * (PAD * 2) + ((lane & 16) ? 16u : 0u);
    const uint32_t b_lane = (uint32_t)(lane & 15) * (PAD * 2);

    float acc[2][8][4] = {};

#pragma unroll
    for (int p = 0; p < 3; p++) {
        const uint32_t abase = sb + (p == 2 ? A_LO_OFF : A_HI_OFF) + (uint32_t)m0 * (PAD * 2) + a_lane;
        const uint32_t bbase = sb + (p == 1 ? B_LO_OFF : B_HI_OFF) + b_lane + (uint32_t)n0 * 2;
#pragma unroll
        for (int ks = 0; ks < 8; ks++) {
            uint32_t ar[2][4];
            ldsm_x4(ar[0], abase + ks * 32);
            ldsm_x4(ar[1], abase + 16 * PAD * 2 + ks * 32);
            const uint32_t bk = bbase + (uint32_t)ks * 16 * PAD * 2;
#pragma unroll
            for (int nt = 0; nt < 8; nt++) {
                uint32_t br[2];
                ldsm_x2t(br, bk + nt * 16);
                mma_bf16(acc[0][nt], ar[0], br);
                mma_bf16(acc[1][nt], ar[1], br);
            }
        }
    }

    // epilogue: H + AGG(self-loop+bias)
    const int g = lane >> 2, tig = lane & 3;
#pragma unroll
    for (int mt = 0; mt < 2; mt++) {
#pragma unroll
        for (int half = 0; half < 2; half++) {
            int r = r0 + m0 + mt * 16 + g + half * 8;
            if (r < n) {
                float d = g_dis[r];
                float d2 = d * d;
#pragma unroll
                for (int nt = 0; nt < 8; nt++) {
                    int c = n0 + nt * 8 + tig * 2;
                    float h0 = acc[mt][nt][half * 2], h1 = acc[mt][nt][half * 2 + 1];
                    float2 bb = *(const float2*)&bias[c];
                    *(float2*)&H[(size_t)r * 128 + c] = make_float2(h0, h1);
                    *(float2*)&AGG[(size_t)r * 128 + c] =
                        make_float2(fmaf(h0, d2, bb.x), fmaf(h1, d2, bb.y));
                }
            }
        }
    }
}

// ---------------- FFMA GEMM for the 32-wide final layer ----------------
template <int M>
__global__ void k_gemm(const float* __restrict__ X, const float* __restrict__ W,
                       float* __restrict__ H, int n) {
    extern __shared__ float sm[];
    float* sW = sm;
    float* sX = sm + 128 * M;
    const int T = blockDim.x;

    for (int i = threadIdx.x; i < 128 * M / 4; i += T)
        ((float4*)sW)[i] = ((const float4*)W)[i];

    const int cg = threadIdx.x % (M / 4);
    const int rg = threadIdx.x / (M / 4);
    const int ntiles = (n + 31) / 32;

    for (int tile = blockIdx.x; tile < ntiles; tile += gridDim.x) {
        int r0 = tile * 32;
        __syncthreads();
        for (int i = threadIdx.x; i < 32 * 32; i += T) {
            int rr = i >> 5, cc = i & 31;
            float4 v = make_float4(0.f, 0.f, 0.f, 0.f);
            if (r0 + rr < n)
                v = ((const float4*)(X + (long long)(r0 + rr) * 128))[cc];
            *(float4*)&sX[rr * 132 + cc * 4] = v;
        }
        __syncthreads();

        float acc[4][4];
#pragma unroll
        for (int i = 0; i < 4; i++)
#pragma unroll
            for (int j = 0; j < 4; j++) acc[i][j] = 0.0f;

#pragma unroll 8
        for (int k = 0; k < 128; k++) {
            float4 wv = *(float4*)&sW[k * M + cg * 4];
#pragma unroll
            for (int i = 0; i < 4; i++) {
                float xv = sX[(rg * 4 + i) * 132 + k];
                acc[i][0] += xv * wv.x;
                acc[i][1] += xv * wv.y;
                acc[i][2] += xv * wv.z;
                acc[i][3] += xv * wv.w;
            }
        }
#pragma unroll
        for (int i = 0; i < 4; i++) {
            int r = r0 + rg * 4 + i;
            if (r < n)
                *(float4*)&H[(long long)r * M + cg * 4] =
                    make_float4(acc[i][0], acc[i][1], acc[i][2], acc[i][3]);
        }
    }
}

// ---------------- CSR aggregation (128-wide) + fused BN stats ----------------
__global__ void k_agg128(const float* __restrict__ H, const float* __restrict__ bias,
                         float* __restrict__ AGG, int n) {
    __shared__ float s_rows[8][FDIM];
    __shared__ int s_valid[8];
    const int tid = threadIdx.x;
    const int lane = tid & 31, wid = tid >> 5;
    int v = (blockIdx.x * blockDim.x + tid) >> 5;
    const bool valid = (v < n);
    if (lane == 0) s_valid[wid] = valid ? 1 : 0;

    float4 acc = make_float4(0.f, 0.f, 0.f, 0.f);
    if (valid) {
        const float dv = g_dis[v];
        const int e0 = g_off[v], e1 = g_off[v + 1];
        acc = ((const float4*)bias)[lane];
        {
            float4 hv = ((const float4*)(H + (long long)v * FDIM))[lane];
            float d2 = dv * dv;
            acc.x = fmaf(hv.x, d2, acc.x); acc.y = fmaf(hv.y, d2, acc.y);
            acc.z = fmaf(hv.z, d2, acc.z); acc.w = fmaf(hv.w, d2, acc.w);
        }
        int e = e0;
        for (; e + 1 < e1; e += 2) {
            int s0 = __ldg(&g_esrc[e]);
            int s1 = __ldg(&g_esrc[e + 1]);
            float n0 = g_dis[s0] * dv;
            float n1 = g_dis[s1] * dv;
            float4 a = ((const float4*)(H + (long long)s0 * FDIM))[lane];
            float4 b = ((const float4*)(H + (long long)s1 * FDIM))[lane];
            acc.x = fmaf(a.x, n0, acc.x); acc.y = fmaf(a.y, n0, acc.y);
            acc.z = fmaf(a.z, n0, acc.z); acc.w = fmaf(a.w, n0, acc.w);
            acc.x = fmaf(b.x, n1, acc.x); acc.y = fmaf(b.y, n1, acc.y);
            acc.z = fmaf(b.z, n1, acc.z); acc.w = fmaf(b.w, n1, acc.w);
        }
        if (e < e1) {
            int s0 = __ldg(&g_esrc[e]);
            float n0 = g_dis[s0] * dv;
            float4 a = ((const float4*)(H + (long long)s0 * FDIM))[lane];
            acc.x = fmaf(a.x, n0, acc.x); acc.y = fmaf(a.y, n0, acc.y);
            acc.z = fmaf(a.z, n0, acc.z); acc.w = fmaf(a.w, n0, acc.w);
        }
        ((float4*)(AGG + (long long)v * FDIM))[lane] = acc;
    }
    *(float4*)&s_rows[wid][lane * 4] = acc;
    __syncthreads();

    // block-level BN partials: thread t -> col c = t & 127, part = t >> 7
    int c = tid & 127;
    int part = tid >> 7;
    float s = 0.0f;
#pragma unroll
    for (int w = 0; w < 8; w++) {
        if (s_valid[w]) {
            float val = s_rows[w][c];
            s += part ? val * val : val;
        }
    }
    atomicAdd(part ? &g_sumsq[c] : &g_sum[c], s);
}

// ---------------- CSR aggregation (32-wide) fused with log_softmax ----------------
__global__ void k_agg32_lsm(const float* __restrict__ H2, const float* __restrict__ bias,
                            float* __restrict__ out, int n) {
    int v = (blockIdx.x * blockDim.x + threadIdx.x) >> 5;
    if (v >= n) return;
    const int lane = threadIdx.x & 31;
    const float dv = g_dis[v];
    const int e0 = g_off[v], e1 = g_off[v + 1];

    float acc = bias[lane] + H2[(long long)v * ODIM + lane] * dv * dv;
    int e = e0;
    for (; e + 1 < e1; e += 2) {
        int s0 = __ldg(&g_esrc[e]);
        int s1 = __ldg(&g_esrc[e + 1]);
        float n0 = g_dis[s0] * dv;
        float n1 = g_dis[s1] * dv;
        float a = H2[(long long)s0 * ODIM + lane];
        float b = H2[(long long)s1 * ODIM + lane];
        acc = fmaf(a, n0, acc);
        acc = fmaf(b, n1, acc);
    }
    if (e < e1) {
        int s0 = __ldg(&g_esrc[e]);
        acc = fmaf(H2[(long long)s0 * ODIM + lane], g_dis[s0] * dv, acc);
    }
    float m = acc;
#pragma unroll
    for (int o = 16; o; o >>= 1) m = fmaxf(m, __shfl_xor_sync(0xffffffffu, m, o));
    float ex = expf(acc - m);
    float s = ex;
#pragma unroll
    for (int o = 16; o; o >>= 1) s += __shfl_xor_sync(0xffffffffu, s, o);
    out[(long long)v * ODIM + lane] = acc - m - logf(s);
}

// ---------------- BN zero / apply ----------------
__global__ void k_zero_stats() {
    int i = threadIdx.x;
    if (i < FDIM) { g_sum[i] = 0.0f; g_sumsq[i] = 0.0f; }
}
__global__ void k_apply(const float* __restrict__ AGG, const float* __restrict__ gam,
                        const float* __restrict__ bet, const float* __restrict__ XRES,
                        float* __restrict__ XOUT, int n) {
    long long i = (long long)blockIdx.x * blockDim.x + threadIdx.x;
    long long tot = (long long)n * (FDIM / 4);
    if (i >= tot) return;
    int c4 = (int)(i % (FDIM / 4));
    float inv = 1.0f / (float)n;
    float4 a = ((const float4*)AGG)[i];
    float4 r = ((const float4*)XRES)[i];
    float av[4] = {a.x, a.y, a.z, a.w};
    float rv[4] = {r.x, r.y, r.z, r.w};
    float o[4];
#pragma unroll
    for (int j = 0; j < 4; j++) {
        int c = c4 * 4 + j;
        float mu = g_sum[c] * inv;
        float var = g_sumsq[c] * inv - mu * mu;
        float rstd = rsqrtf(var + 1e-5f);
        float y = (av[j] - mu) * rstd * gam[c] + bet[c];
        o[j] = fmaxf(y, 0.0f) + rv[j];
    }
    ((float4*)XOUT)[i] = make_float4(o[0], o[1], o[2], o[3]);
}

// ---------------- launch ----------------
extern "C" void kernel_launch(void* const* d_in, const int* in_sizes, int n_in,
                              void* d_out, int out_size) {
    const float* x   = (const float*)d_in[0];
    const void*  ei  = d_in[1];
    const float* W0  = (const float*)d_in[2];
    const float* b0  = (const float*)d_in[3];
    const float* gm0 = (const float*)d_in[4];
    const float* be0 = (const float*)d_in[5];
    const float* W1  = (const float*)d_in[6];
    const float* b1  = (const float*)d_in[7];
    const float* gm1 = (const float*)d_in[8];
    const float* be1 = (const float*)d_in[9];
    const float* W2  = (const float*)d_in[10];
    const float* b2  = (const float*)d_in[11];
    float* out = (float*)d_out;

    const int n = in_sizes[0] / FDIM;   // 50000
    const int E = in_sizes[1] / 2;      // 800000

    float *p_h, *p_agg, *p_xc, *p_h2;
    cudaGetSymbolAddress((void**)&p_h, g_h);
    cudaGetSymbolAddress((void**)&p_agg, g_agg);
    cudaGetSymbolAddress((void**)&p_xc, g_xc);
    cudaGetSymbolAddress((void**)&p_h2, g_h2);

    cudaFuncSetAttribute(k_mma128, cudaFuncAttributeMaxDynamicSharedMemorySize, MMA_SMEM);
    const int SMEM32 = 128 * 32 * 4 + 32 * 132 * 4;
    cudaFuncSetAttribute(k_gemm<32>, cudaFuncAttributeMaxDynamicSharedMemorySize, SMEM32);

    const int elem128_blocks = (int)(((long long)n * (FDIM / 4) + 255) / 256);
    const int node_warp_blocks = (n + 7) / 8;
    const int mma_blocks = (n + 63) / 64;

    // ---- graph preprocessing ----
    k_detect<<<1, 256>>>((const unsigned*)ei);
    k_zero_int<<<(NNODES + 255) / 256, 256>>>();
    k_hist<<<(E + 255) / 256, 256>>>(ei, E);
    k_dis<<<(NNODES + 255) / 256, 256>>>();
    k_prefix<<<1, 1024>>>();
    k_fill<<<(E + 255) / 256, 256>>>(ei, E);

    // ---- block 0 ----
    k_mma128<<<mma_blocks, 128, MMA_SMEM>>>(x, W0, b0, p_h, p_agg, n);
    k_zero_stats<<<1, 128>>>();
    k_agg128<<<node_warp_blocks, 256>>>(p_h, b0, p_agg, n);
    k_apply<<<elem128_blocks, 256>>>(p_agg, gm0, be0, x, p_xc, n);

    // ---- block 1 ----
    k_mma128<<<mma_blocks, 128, MMA_SMEM>>>(p_xc, W1, b1, p_h, p_agg, n);
    k_zero_stats<<<1, 128>>>();
    k_agg128<<<node_warp_blocks, 256>>>(p_h, b1, p_agg, n);
    k_apply<<<elem128_blocks, 256>>>(p_agg, gm1, be1, p_xc, p_xc, n);

    // ---- final conv + fused log_softmax ----
    k_gemm<32><<<888, 64, SMEM32>>>(p_xc, W2, p_h2, n);
    k_agg32_lsm<<<node_warp_blocks, 256>>>(p_h2, b2, out, n);
}